// round 13
// baseline (speedup 1.0000x reference)
#include <cuda_runtime.h>
#include <cuda_fp8.h>
#include <cstdint>
#include <math.h>

// ---------------------------------------------------------------------------
// Problem constants (fixed shapes: x,y = [4096,1024] fp32, scalar output)
// ---------------------------------------------------------------------------
#define BROWS 4096
#define DDIM  1024
#define EPSF  1e-6f

// fp8 quantization pre-scale: e4m3 of 16*component; acc = 256*S.
// exp(S/tau) = exp2(acc * log2(e) / (0.07 * 256))
#define QSCALE 16.0f
#define K2LOG_S (20.6099287984152302f / 256.0f)

// R12 ncu: tensor pipe only 43.6% busy -> GEMM is latency/issue-bound.
// R13: warp tile 32x64 (BM=128, BN=256) doubles tensor work per warp per
// chunk (16 QMMA per kk vs 8) with ~constant per-chunk overhead.
#define BM 128
#define BN 256
#define BK 128
#define KT 8
#define STAGES 4
#define RS (BK + 16)
#define STAGE_BYTES ((BM + BN) * RS)             // 55296
#define SMEM_BYTES (STAGES * STAGE_BYTES)        // 221184 (<= 232448 opt-in)
#define NSM 148
#define NTILES 512                               // 32 x 16
#define NWARPG (NSM * 16)

// ---------------------------------------------------------------------------
// Scratch (device globals: allocation-free rule; zero-initialized)
// ---------------------------------------------------------------------------
__device__ uint8_t g_xq[(size_t)BROWS * DDIM];
__device__ uint8_t g_yq[(size_t)BROWS * DDIM];
__device__ float g_rowsum[BROWS];
__device__ float g_colsum[BROWS];
__device__ float g_diag[BROWS];
__device__ int g_cnt[32];     // row blocks of 128; ==128 when block ready
__device__ int g_done;        // CTA completion counter

// ---------------------------------------------------------------------------
// PTX helpers (<= sm_89; nothing 'a'-gated)
// ---------------------------------------------------------------------------
static __device__ __forceinline__ uint32_t smem_u32(const void* p) {
    uint32_t a;
    asm("{ .reg .u64 t; cvta.to.shared.u64 t, %1; cvt.u32.u64 %0, t; }"
        : "=r"(a) : "l"(p));
    return a;
}
static __device__ __forceinline__ float ex2f(float x) {
    float y;
    asm("ex2.approx.ftz.f32 %0, %1;" : "=f"(y) : "f"(x));
    return y;
}
static __device__ __forceinline__ void cp16(uint32_t dst, const void* src) {
    asm volatile("cp.async.cg.shared.global [%0], [%1], 16;"
                 :: "r"(dst), "l"(src) : "memory");
}
#define CP_COMMIT() asm volatile("cp.async.commit_group;" ::: "memory")
#define CP_WAIT(n)  asm volatile("cp.async.wait_group %0;" :: "n"(n) : "memory")

static __device__ __forceinline__ void ldmatrix_x4(
    uint32_t& r0, uint32_t& r1, uint32_t& r2, uint32_t& r3, uint32_t addr) {
    asm volatile("ldmatrix.sync.aligned.m8n8.x4.shared.b16 {%0,%1,%2,%3}, [%4];"
                 : "=r"(r0), "=r"(r1), "=r"(r2), "=r"(r3) : "r"(addr));
}
static __device__ __forceinline__ void mma16832(
    float* d, const uint32_t* a, const uint32_t* b) {
    asm volatile(
        "mma.sync.aligned.m16n8k32.row.col.f32.e4m3.e4m3.f32 "
        "{%0,%1,%2,%3}, {%4,%5,%6,%7}, {%8,%9}, {%0,%1,%2,%3};"
        : "+f"(d[0]), "+f"(d[1]), "+f"(d[2]), "+f"(d[3])
        : "r"(a[0]), "r"(a[1]), "r"(a[2]), "r"(a[3]), "r"(b[0]), "r"(b[1]));
}
static __device__ __forceinline__ uint32_t pack_fp8x4(
    float a, float b, float c, float d) {
    const __nv_fp8x2_storage_t lo =
        __nv_cvt_float2_to_fp8x2(make_float2(a, b), __NV_SATFINITE, __NV_E4M3);
    const __nv_fp8x2_storage_t hi =
        __nv_cvt_float2_to_fp8x2(make_float2(c, d), __NV_SATFINITE, __NV_E4M3);
    return (uint32_t)lo | ((uint32_t)hi << 16);
}

// tid 0 spins on one x block and two y blocks (BN=256 spans 2 blocks).
static __device__ __forceinline__ void wait_blocks_t0(int xb, int yb, int tid) {
    if (tid == 0) {
        volatile int* c = g_cnt;
        while (c[xb] != 128) {}
        while (c[yb] != 128) {}
        while (c[yb + 1] != 128) {}
        __threadfence();
    }
}

// A: 128 rows, B: 256 rows, 8 x 16B chunks each = 3072 cp16 / 512 threads = 6
static __device__ __forceinline__ void load_chunk(
    uint32_t sbase, int stage, int chunk,
    const uint8_t* gA, const uint8_t* gB, int tid) {
    const uint32_t aBase = sbase + (uint32_t)(stage * STAGE_BYTES);
    const uint32_t bBase = aBase + (uint32_t)(BM * RS);
#pragma unroll
    for (int r = 0; r < 2; ++r) {
        const int idx = tid + r * 512;
        const int row = idx >> 3, c = idx & 7;
        cp16(aBase + (uint32_t)(row * RS + c * 16),
             gA + (size_t)(chunk * BK) + (size_t)row * DDIM + c * 16);
    }
#pragma unroll
    for (int r = 0; r < 4; ++r) {
        const int idx = tid + r * 512;
        const int row = idx >> 3, c = idx & 7;
        cp16(bBase + (uint32_t)(row * RS + c * 16),
             gB + (size_t)(chunk * BK) + (size_t)row * DDIM + c * 16);
    }
    CP_COMMIT();
}

// ---------------------------------------------------------------------------
// The fused persistent kernel: grid = 148 x 512 threads
// ---------------------------------------------------------------------------
__global__ void __launch_bounds__(512, 1) fused_kernel(
    const float* __restrict__ x, const float* __restrict__ y,
    float* __restrict__ out) {
    extern __shared__ uint8_t smem[];
    __shared__ int sdone;
    const uint32_t sbase = smem_u32(smem);
    const int tid = threadIdx.x;
    const int lane = tid & 31;
    const int wid = tid >> 5;

    // ========== Phase A: normalize + quantize (warp-per-row, read ONCE) =====
    for (int r = blockIdx.x * 16 + wid; r < BROWS; r += NWARPG) {
        const float4* xr = reinterpret_cast<const float4*>(x) + (size_t)r * 256;
        const float4* yr = reinterpret_cast<const float4*>(y) + (size_t)r * 256;
        float4 xv[8], yv[8];
#pragma unroll
        for (int u = 0; u < 8; ++u) xv[u] = xr[lane + 32 * u];
#pragma unroll
        for (int u = 0; u < 8; ++u) yv[u] = yr[lane + 32 * u];

        float ssx = 0.f, ssy = 0.f, sxy = 0.f;
#pragma unroll
        for (int u = 0; u < 8; ++u) {
            ssx += xv[u].x * xv[u].x + xv[u].y * xv[u].y
                 + xv[u].z * xv[u].z + xv[u].w * xv[u].w;
            ssy += yv[u].x * yv[u].x + yv[u].y * yv[u].y
                 + yv[u].z * yv[u].z + yv[u].w * yv[u].w;
            sxy += xv[u].x * yv[u].x + xv[u].y * yv[u].y
                 + xv[u].z * yv[u].z + xv[u].w * yv[u].w;
        }
#pragma unroll
        for (int m = 16; m; m >>= 1) {
            ssx += __shfl_xor_sync(0xffffffffu, ssx, m);
            ssy += __shfl_xor_sync(0xffffffffu, ssy, m);
            sxy += __shfl_xor_sync(0xffffffffu, sxy, m);
        }
        const float invx = 1.0f / fmaxf(sqrtf(ssx), EPSF);
        const float invy = 1.0f / fmaxf(sqrtf(ssy), EPSF);
        if (lane == 0) {
            g_diag[r] = sxy * invx * invy;
            g_rowsum[r] = 0.f;
            g_colsum[r] = 0.f;
        }
        const float qx = QSCALE * invx, qy = QSCALE * invy;
        uint32_t* ox = reinterpret_cast<uint32_t*>(g_xq + (size_t)r * DDIM);
        uint32_t* oy = reinterpret_cast<uint32_t*>(g_yq + (size_t)r * DDIM);
#pragma unroll
        for (int u = 0; u < 8; ++u) {
            ox[lane + 32 * u] =
                pack_fp8x4(xv[u].x * qx, xv[u].y * qx, xv[u].z * qx, xv[u].w * qx);
            oy[lane + 32 * u] =
                pack_fp8x4(yv[u].x * qy, yv[u].y * qy, yv[u].z * qy, yv[u].w * qy);
        }
        __threadfence();
        if (lane == 0) atomicAdd(&g_cnt[r >> 7], 1);
    }

    // ================= Phase B: persistent GEMM, warp tile 32x64 ============
    const int warp_m = wid & 3;        // 32-row slice
    const int warp_n = wid >> 2;       // 64-col slice
    const int gid = lane >> 2, tig = lane & 3;
    const uint32_t lrow = (uint32_t)(lane & 15);
    const uint32_t koff = (uint32_t)((lane >> 4) * 16);

    int t = blockIdx.x;
    const uint8_t* gA = g_xq + (size_t)((t & 31) * BM) * DDIM;
    const uint8_t* gB = g_yq + (size_t)((t >> 5) * BN) * DDIM;

    if (t < NTILES) {
        wait_blocks_t0(t & 31, (t >> 5) * 2, tid);
        __syncthreads();
        load_chunk(sbase, 0, 0, gA, gB, tid);
        load_chunk(sbase, 1, 1, gA, gB, tid);
        load_chunk(sbase, 2, 2, gA, gB, tid);
    }

    while (t < NTILES) {
        const int i_base = (t & 31) * BM;
        const int j_base = (t >> 5) * BN;
        const int nxt = t + NSM;
        const bool has_nxt = (nxt < NTILES);
        const uint8_t* gA2 = g_xq + (size_t)((nxt & 31) * BM) * DDIM;
        const uint8_t* gB2 = g_yq + (size_t)((nxt >> 5) * BN) * DDIM;

        float acc[2][8][4];
#pragma unroll
        for (int mi = 0; mi < 2; ++mi)
#pragma unroll
            for (int ni = 0; ni < 8; ++ni)
#pragma unroll
                for (int r = 0; r < 4; ++r) acc[mi][ni][r] = 0.f;

        for (int kt = 0; kt < KT; ++kt) {
            CP_WAIT(STAGES - 2);
            __syncthreads();
            const int p = kt + STAGES - 1;
            if (p < KT) {
                load_chunk(sbase, p & 3, p, gA, gB, tid);
            } else if (has_nxt) {
                if (kt == 5) {
                    wait_blocks_t0(nxt & 31, (nxt >> 5) * 2, tid);
                    __syncthreads();
                }
                load_chunk(sbase, p & 3, p - KT, gA2, gB2, tid);
            } else {
                CP_COMMIT();
            }

            const uint32_t aTile = sbase + (uint32_t)((kt & 3) * STAGE_BYTES);
            const uint32_t bTile = aTile + (uint32_t)(BM * RS);
            const uint32_t aAddr0 = aTile + (warp_m * 32 + lrow) * RS + koff;
            const uint32_t bAddr0 = bTile + (warp_n * 64 + lrow) * RS + koff;

#pragma unroll
            for (int kk = 0; kk < 4; ++kk) {
                const uint32_t kb = (uint32_t)(kk * 32);
                uint32_t a[2][4];
#pragma unroll
                for (int mi = 0; mi < 2; ++mi)
                    ldmatrix_x4(a[mi][0], a[mi][1], a[mi][2], a[mi][3],
                                aAddr0 + kb + (uint32_t)(mi * 16 * RS));
                uint32_t b[8][2];
#pragma unroll
                for (int p2 = 0; p2 < 4; ++p2) {
                    uint32_t r0, r1, r2, r3;
                    ldmatrix_x4(r0, r1, r2, r3,
                                bAddr0 + kb + (uint32_t)(p2 * 16 * RS));
                    b[2 * p2][0] = r0; b[2 * p2 + 1][0] = r1;
                    b[2 * p2][1] = r2; b[2 * p2 + 1][1] = r3;
                }
#pragma unroll
                for (int mi = 0; mi < 2; ++mi)
#pragma unroll
                    for (int ni = 0; ni < 8; ++ni)
                        mma16832(acc[mi][ni], a[mi], b[ni]);
            }
        }

        // -------- fused epilogue: exp + row/col sums --------
        float rs[2][2] = {{0.f, 0.f}, {0.f, 0.f}};
        float cs[8][2];
#pragma unroll
        for (int ni = 0; ni < 8; ++ni) { cs[ni][0] = 0.f; cs[ni][1] = 0.f; }

#pragma unroll
        for (int mi = 0; mi < 2; ++mi)
#pragma unroll
            for (int ni = 0; ni < 8; ++ni) {
                const float e0 = ex2f(acc[mi][ni][0] * K2LOG_S);
                const float e1 = ex2f(acc[mi][ni][1] * K2LOG_S);
                const float e2 = ex2f(acc[mi][ni][2] * K2LOG_S);
                const float e3 = ex2f(acc[mi][ni][3] * K2LOG_S);
                rs[mi][0] += e0 + e1;
                rs[mi][1] += e2 + e3;
                cs[ni][0] += e0 + e2;
                cs[ni][1] += e1 + e3;
            }

        const int m0 = i_base + warp_m * 32;
        const int n0 = j_base + warp_n * 64;
#pragma unroll
        for (int mi = 0; mi < 2; ++mi)
#pragma unroll
            for (int h = 0; h < 2; ++h) {
                float v = rs[mi][h];
                v += __shfl_xor_sync(0xffffffffu, v, 1);
                v += __shfl_xor_sync(0xffffffffu, v, 2);
                if (tig == 0)
                    atomicAdd(&g_rowsum[m0 + mi * 16 + h * 8 + gid], v);
            }
#pragma unroll
        for (int ni = 0; ni < 8; ++ni)
#pragma unroll
            for (int h = 0; h < 2; ++h) {
                float v = cs[ni][h];
                v += __shfl_xor_sync(0xffffffffu, v, 4);
                v += __shfl_xor_sync(0xffffffffu, v, 8);
                v += __shfl_xor_sync(0xffffffffu, v, 16);
                if (gid == 0)
                    atomicAdd(&g_colsum[n0 + ni * 8 + 2 * tig + h], v);
            }

        if (!has_nxt) break;
        t = nxt;
        gA = gA2;
        gB = gB2;
    }

    // ================= Phase C: last CTA finalizes + resets =================
    __threadfence();
    __syncthreads();
    if (tid == 0) sdone = (atomicAdd(&g_done, 1) == NSM - 1) ? 1 : 0;
    __syncthreads();
    if (sdone) {
        __threadfence();
        const float extra = (float)BROWS * 1e-6f + 1e-6f;
        float acc = 0.f;
#pragma unroll
        for (int i = tid; i < BROWS; i += 512) {
            acc += (2.0f / 0.07f) * g_diag[i]
                 - logf(g_rowsum[i] + extra)
                 - logf(g_colsum[i] + extra);
        }
        float* sb = reinterpret_cast<float*>(smem);
        sb[tid] = acc;
        __syncthreads();
#pragma unroll
        for (int s = 256; s; s >>= 1) {
            if (tid < s) sb[tid] += sb[tid + s];
            __syncthreads();
        }
        if (tid == 0) out[0] = sb[0] * (-1.0f / (2.0f * (float)BROWS));
        // reset handshake state for the next graph replay
        if (tid < 32) g_cnt[tid] = 0;
        if (tid == 0) g_done = 0;
    }
}

// ---------------------------------------------------------------------------
extern "C" void kernel_launch(void* const* d_in, const int* in_sizes, int n_in,
                              void* d_out, int out_size) {
    const float* x = (const float*)d_in[0];
    const float* y = (const float*)d_in[1];
    float* out = (float*)d_out;

    static int configured = 0;
    if (!configured) {
        cudaFuncSetAttribute(fused_kernel,
                             cudaFuncAttributeMaxDynamicSharedMemorySize, SMEM_BYTES);
        configured = 1;
    }

    fused_kernel<<<NSM, 512, SMEM_BYTES>>>(x, y, out);
}

// round 14
// speedup vs baseline: 1.0168x; 1.0168x over previous
#include <cuda_runtime.h>
#include <cuda_fp8.h>
#include <cstdint>
#include <math.h>

// ---------------------------------------------------------------------------
// Problem constants (fixed shapes: x,y = [4096,1024] fp32, scalar output)
// ---------------------------------------------------------------------------
#define BROWS 4096
#define DDIM  1024
#define EPSF  1e-6f

// fp8 quantization pre-scale: e4m3 of 16*component; acc = 256*S.
// exp(S/tau) = exp2(acc * log2(e) / (0.07 * 256))
#define QSCALE 16.0f
#define K2LOG_S (20.6099287984152302f / 256.0f)

// R13 post-mortem: tensor util pinned at 42% with 14.6 cyc/QMMA issue gap vs
// ~6 cyc pipe occupancy -> warps stall on LDSM->MMA RAW each kk step.
// R14 = R12 config (130.1us best) + FRAGMENT DOUBLE-BUFFERING: prefetch
// kk+1's ldmatrix fragments while kk's MMAs run (acc32 + frags2x24 + misc
// ~90 regs < 128 cap, no spills).
#define BM 128
#define BN 128
#define BK 128
#define KT 8
#define STAGES 4
#define RS (BK + 16)
#define STAGE_BYTES ((BM + BN) * RS)             // 36864
#define SMEM_BYTES (STAGES * STAGE_BYTES)        // 147456
#define NSM 148
#define NTILES 1024
#define NWARPG (NSM * 16)

// ---------------------------------------------------------------------------
// Scratch (device globals: allocation-free rule; zero-initialized)
// ---------------------------------------------------------------------------
__device__ uint8_t g_xq[(size_t)BROWS * DDIM];
__device__ uint8_t g_yq[(size_t)BROWS * DDIM];
__device__ float g_rowsum[BROWS];
__device__ float g_colsum[BROWS];
__device__ float g_diag[BROWS];
__device__ int g_cnt[32];     // row blocks of 128; ==128 when block ready
__device__ int g_done;        // CTA completion counter

// ---------------------------------------------------------------------------
// PTX helpers (<= sm_89; nothing 'a'-gated)
// ---------------------------------------------------------------------------
static __device__ __forceinline__ uint32_t smem_u32(const void* p) {
    uint32_t a;
    asm("{ .reg .u64 t; cvta.to.shared.u64 t, %1; cvt.u32.u64 %0, t; }"
        : "=r"(a) : "l"(p));
    return a;
}
static __device__ __forceinline__ float ex2f(float x) {
    float y;
    asm("ex2.approx.ftz.f32 %0, %1;" : "=f"(y) : "f"(x));
    return y;
}
static __device__ __forceinline__ void cp16(uint32_t dst, const void* src) {
    asm volatile("cp.async.cg.shared.global [%0], [%1], 16;"
                 :: "r"(dst), "l"(src) : "memory");
}
#define CP_COMMIT() asm volatile("cp.async.commit_group;" ::: "memory")
#define CP_WAIT(n)  asm volatile("cp.async.wait_group %0;" :: "n"(n) : "memory")

static __device__ __forceinline__ void ldmatrix_x4(
    uint32_t& r0, uint32_t& r1, uint32_t& r2, uint32_t& r3, uint32_t addr) {
    asm volatile("ldmatrix.sync.aligned.m8n8.x4.shared.b16 {%0,%1,%2,%3}, [%4];"
                 : "=r"(r0), "=r"(r1), "=r"(r2), "=r"(r3) : "r"(addr));
}
static __device__ __forceinline__ void mma16832(
    float* d, const uint32_t* a, const uint32_t* b) {
    asm volatile(
        "mma.sync.aligned.m16n8k32.row.col.f32.e4m3.e4m3.f32 "
        "{%0,%1,%2,%3}, {%4,%5,%6,%7}, {%8,%9}, {%0,%1,%2,%3};"
        : "+f"(d[0]), "+f"(d[1]), "+f"(d[2]), "+f"(d[3])
        : "r"(a[0]), "r"(a[1]), "r"(a[2]), "r"(a[3]), "r"(b[0]), "r"(b[1]));
}
static __device__ __forceinline__ uint32_t pack_fp8x4(
    float a, float b, float c, float d) {
    const __nv_fp8x2_storage_t lo =
        __nv_cvt_float2_to_fp8x2(make_float2(a, b), __NV_SATFINITE, __NV_E4M3);
    const __nv_fp8x2_storage_t hi =
        __nv_cvt_float2_to_fp8x2(make_float2(c, d), __NV_SATFINITE, __NV_E4M3);
    return (uint32_t)lo | ((uint32_t)hi << 16);
}

// tid 0 spins; caller must follow with __syncthreads() before consuming.
static __device__ __forceinline__ void wait_blocks_t0(int xb, int yb, int tid) {
    if (tid == 0) {
        volatile int* c = g_cnt;
        while (c[xb] != 128) {}
        while (c[yb] != 128) {}
        __threadfence();
    }
}

static __device__ __forceinline__ void load_chunk(
    uint32_t sbase, int stage, int chunk,
    const uint8_t* gA, const uint8_t* gB, int tid) {
    const uint32_t aBase = sbase + (uint32_t)(stage * STAGE_BYTES);
    const uint32_t bBase = aBase + (uint32_t)(BM * RS);
#pragma unroll
    for (int r = 0; r < 2; ++r) {
        const int idx = tid + r * 512;
        const int row = idx >> 3, c = idx & 7;
        cp16(aBase + (uint32_t)(row * RS + c * 16),
             gA + (size_t)(chunk * BK) + (size_t)row * DDIM + c * 16);
        cp16(bBase + (uint32_t)(row * RS + c * 16),
             gB + (size_t)(chunk * BK) + (size_t)row * DDIM + c * 16);
    }
    CP_COMMIT();
}

// load one kk-step's A fragments (2x ldmatrix.x4) and B fragments (2x)
static __device__ __forceinline__ void load_frags(
    uint32_t aAddr0, uint32_t bAddr0, uint32_t kb,
    uint32_t a[2][4], uint32_t b[4][2]) {
#pragma unroll
    for (int mi = 0; mi < 2; ++mi)
        ldmatrix_x4(a[mi][0], a[mi][1], a[mi][2], a[mi][3],
                    aAddr0 + kb + (uint32_t)(mi * 16 * RS));
#pragma unroll
    for (int p2 = 0; p2 < 2; ++p2) {
        uint32_t r0, r1, r2, r3;
        ldmatrix_x4(r0, r1, r2, r3, bAddr0 + kb + (uint32_t)(p2 * 16 * RS));
        b[2 * p2][0] = r0; b[2 * p2 + 1][0] = r1;
        b[2 * p2][1] = r2; b[2 * p2 + 1][1] = r3;
    }
}

// ---------------------------------------------------------------------------
// The fused persistent kernel: grid = 148 x 512 threads
// ---------------------------------------------------------------------------
__global__ void __launch_bounds__(512, 1) fused_kernel(
    const float* __restrict__ x, const float* __restrict__ y,
    float* __restrict__ out) {
    extern __shared__ uint8_t smem[];
    __shared__ int sdone;
    const uint32_t sbase = smem_u32(smem);
    const int tid = threadIdx.x;
    const int lane = tid & 31;
    const int wid = tid >> 5;

    // ========== Phase A: normalize + quantize (warp-per-row, read ONCE) =====
    for (int r = blockIdx.x * 16 + wid; r < BROWS; r += NWARPG) {
        const float4* xr = reinterpret_cast<const float4*>(x) + (size_t)r * 256;
        const float4* yr = reinterpret_cast<const float4*>(y) + (size_t)r * 256;
        float4 xv[8], yv[8];
#pragma unroll
        for (int u = 0; u < 8; ++u) xv[u] = xr[lane + 32 * u];
#pragma unroll
        for (int u = 0; u < 8; ++u) yv[u] = yr[lane + 32 * u];

        float ssx = 0.f, ssy = 0.f, sxy = 0.f;
#pragma unroll
        for (int u = 0; u < 8; ++u) {
            ssx += xv[u].x * xv[u].x + xv[u].y * xv[u].y
                 + xv[u].z * xv[u].z + xv[u].w * xv[u].w;
            ssy += yv[u].x * yv[u].x + yv[u].y * yv[u].y
                 + yv[u].z * yv[u].z + yv[u].w * yv[u].w;
            sxy += xv[u].x * yv[u].x + xv[u].y * yv[u].y
                 + xv[u].z * yv[u].z + xv[u].w * yv[u].w;
        }
#pragma unroll
        for (int m = 16; m; m >>= 1) {
            ssx += __shfl_xor_sync(0xffffffffu, ssx, m);
            ssy += __shfl_xor_sync(0xffffffffu, ssy, m);
            sxy += __shfl_xor_sync(0xffffffffu, sxy, m);
        }
        const float invx = 1.0f / fmaxf(sqrtf(ssx), EPSF);
        const float invy = 1.0f / fmaxf(sqrtf(ssy), EPSF);
        if (lane == 0) {
            g_diag[r] = sxy * invx * invy;
            g_rowsum[r] = 0.f;
            g_colsum[r] = 0.f;
        }
        const float qx = QSCALE * invx, qy = QSCALE * invy;
        uint32_t* ox = reinterpret_cast<uint32_t*>(g_xq + (size_t)r * DDIM);
        uint32_t* oy = reinterpret_cast<uint32_t*>(g_yq + (size_t)r * DDIM);
#pragma unroll
        for (int u = 0; u < 8; ++u) {
            ox[lane + 32 * u] =
                pack_fp8x4(xv[u].x * qx, xv[u].y * qx, xv[u].z * qx, xv[u].w * qx);
            oy[lane + 32 * u] =
                pack_fp8x4(yv[u].x * qy, yv[u].y * qy, yv[u].z * qy, yv[u].w * qy);
        }
        __threadfence();
        if (lane == 0) atomicAdd(&g_cnt[r >> 7], 1);
    }

    // ================= Phase B: persistent GEMM (frag double-buffered) ======
    const int warp_m = wid & 3;
    const int warp_n = wid >> 2;
    const int gid = lane >> 2, tig = lane & 3;
    const uint32_t lrow = (uint32_t)(lane & 15);
    const uint32_t koff = (uint32_t)((lane >> 4) * 16);

    int t = blockIdx.x;
    const uint8_t* gA = g_xq + (size_t)((t & 31) * BM) * DDIM;
    const uint8_t* gB = g_yq + (size_t)((t >> 5) * BN) * DDIM;

    wait_blocks_t0(t & 31, t >> 5, tid);
    __syncthreads();
    load_chunk(sbase, 0, 0, gA, gB, tid);
    load_chunk(sbase, 1, 1, gA, gB, tid);
    load_chunk(sbase, 2, 2, gA, gB, tid);

    while (true) {
        const int i_base = (t & 31) * BM;
        const int j_base = (t >> 5) * BN;
        const int nxt = t + NSM;
        const bool has_nxt = (nxt < NTILES);
        const uint8_t* gA2 = g_xq + (size_t)((nxt & 31) * BM) * DDIM;
        const uint8_t* gB2 = g_yq + (size_t)((nxt >> 5) * BN) * DDIM;

        float acc[2][4][4];
#pragma unroll
        for (int mi = 0; mi < 2; ++mi)
#pragma unroll
            for (int ni = 0; ni < 4; ++ni)
#pragma unroll
                for (int r = 0; r < 4; ++r) acc[mi][ni][r] = 0.f;

        for (int kt = 0; kt < KT; ++kt) {
            CP_WAIT(STAGES - 2);
            __syncthreads();
            const int p = kt + STAGES - 1;
            if (p < KT) {
                load_chunk(sbase, p & 3, p, gA, gB, tid);
            } else if (has_nxt) {
                if (kt == 5) {
                    wait_blocks_t0(nxt & 31, nxt >> 5, tid);
                    __syncthreads();
                }
                load_chunk(sbase, p & 3, p - KT, gA2, gB2, tid);
            } else {
                CP_COMMIT();
            }

            const uint32_t aTile = sbase + (uint32_t)((kt & 3) * STAGE_BYTES);
            const uint32_t bTile = aTile + (uint32_t)(BM * RS);
            const uint32_t aAddr0 = aTile + (warp_m * 32 + lrow) * RS + koff;
            const uint32_t bAddr0 = bTile + (warp_n * 32 + lrow) * RS + koff;

            uint32_t a[2][2][4], b[2][4][2];
            load_frags(aAddr0, bAddr0, 0, a[0], b[0]);   // prefetch kk=0

#pragma unroll
            for (int kk = 0; kk < 4; ++kk) {
                const int cur = kk & 1;
                if (kk < 3)
                    load_frags(aAddr0, bAddr0, (uint32_t)((kk + 1) * 32),
                               a[cur ^ 1], b[cur ^ 1]);
#pragma unroll
                for (int mi = 0; mi < 2; ++mi)
#pragma unroll
                    for (int ni = 0; ni < 4; ++ni)
                        mma16832(acc[mi][ni], a[cur][mi], b[cur][ni]);
            }
        }

        // -------- fused epilogue: exp + row/col sums --------
        float rs[2][2] = {{0.f, 0.f}, {0.f, 0.f}};
        float cs[4][2];
#pragma unroll
        for (int ni = 0; ni < 4; ++ni) { cs[ni][0] = 0.f; cs[ni][1] = 0.f; }

#pragma unroll
        for (int mi = 0; mi < 2; ++mi)
#pragma unroll
            for (int ni = 0; ni < 4; ++ni) {
                const float e0 = ex2f(acc[mi][ni][0] * K2LOG_S);
                const float e1 = ex2f(acc[mi][ni][1] * K2LOG_S);
                const float e2 = ex2f(acc[mi][ni][2] * K2LOG_S);
                const float e3 = ex2f(acc[mi][ni][3] * K2LOG_S);
                rs[mi][0] += e0 + e1;
                rs[mi][1] += e2 + e3;
                cs[ni][0] += e0 + e2;
                cs[ni][1] += e1 + e3;
            }

        const int m0 = i_base + warp_m * 32;
        const int n0 = j_base + warp_n * 32;
#pragma unroll
        for (int mi = 0; mi < 2; ++mi)
#pragma unroll
            for (int h = 0; h < 2; ++h) {
                float v = rs[mi][h];
                v += __shfl_xor_sync(0xffffffffu, v, 1);
                v += __shfl_xor_sync(0xffffffffu, v, 2);
                if (tig == 0)
                    atomicAdd(&g_rowsum[m0 + mi * 16 + h * 8 + gid], v);
            }
#pragma unroll
        for (int ni = 0; ni < 4; ++ni)
#pragma unroll
            for (int h = 0; h < 2; ++h) {
                float v = cs[ni][h];
                v += __shfl_xor_sync(0xffffffffu, v, 4);
                v += __shfl_xor_sync(0xffffffffu, v, 8);
                v += __shfl_xor_sync(0xffffffffu, v, 16);
                if (gid == 0)
                    atomicAdd(&g_colsum[n0 + ni * 8 + 2 * tig + h], v);
            }

        if (!has_nxt) break;
        t = nxt;
        gA = gA2;
        gB = gB2;
    }

    // ================= Phase C: last CTA finalizes + resets =================
    __threadfence();
    __syncthreads();
    if (tid == 0) sdone = (atomicAdd(&g_done, 1) == NSM - 1) ? 1 : 0;
    __syncthreads();
    if (sdone) {
        __threadfence();
        const float extra = (float)BROWS * 1e-6f + 1e-6f;
        float acc = 0.f;
#pragma unroll
        for (int i = tid; i < BROWS; i += 512) {
            acc += (2.0f / 0.07f) * g_diag[i]
                 - logf(g_rowsum[i] + extra)
                 - logf(g_colsum[i] + extra);
        }
        float* sb = reinterpret_cast<float*>(smem);
        sb[tid] = acc;
        __syncthreads();
#pragma unroll
        for (int s = 256; s; s >>= 1) {
            if (tid < s) sb[tid] += sb[tid + s];
            __syncthreads();
        }
        if (tid == 0) out[0] = sb[0] * (-1.0f / (2.0f * (float)BROWS));
        // reset handshake state for the next graph replay
        if (tid < 32) g_cnt[tid] = 0;
        if (tid == 0) g_done = 0;
    }
}

// ---------------------------------------------------------------------------
extern "C" void kernel_launch(void* const* d_in, const int* in_sizes, int n_in,
                              void* d_out, int out_size) {
    const float* x = (const float*)d_in[0];
    const float* y = (const float*)d_in[1];
    float* out = (float*)d_out;

    static int configured = 0;
    if (!configured) {
        cudaFuncSetAttribute(fused_kernel,
                             cudaFuncAttributeMaxDynamicSharedMemorySize, SMEM_BYTES);
        configured = 1;
    }

    fused_kernel<<<NSM, 512, SMEM_BYTES>>>(x, y, out);
}